// round 16
// baseline (speedup 1.0000x reference)
#include <cuda_runtime.h>
#include <cstdint>

#define RR 8192
#define NX 32
#define FW_S 8
#define FW_W 3
#define NCHAIN (RR/FW_S)         // 1024 chains, one warp each
#define FWPB 4                   // warps per block
#define FW_BLOCKS (NCHAIN/FWPB)  // 256
#define BW_S 32
#define BW_W 5
#define BW_BLOCKS (RR/BW_S)      // 256
#define BNT 256
#define PR_WPB 8
#define VST 36                   // vw/tmp/offT/li row stride (16B aligned)
#define FULLM 0xffffffffu

typedef unsigned long long u64;
union F2U { float f[2]; u64 u; };
union F4U2 { float4 f4; u64 u2[2]; };

__device__ __forceinline__ void ffma2(u64 &acc, u64 x, u64 y) {
    asm("fma.rn.f32x2 %0, %1, %2, %0;" : "+l"(acc) : "l"(x), "l"(y));
}
__device__ __forceinline__ u64 add2(u64 x, u64 y) {
    u64 r; asm("add.rn.f32x2 %0, %1, %2;" : "=l"(r) : "l"(x), "l"(y)); return r;
}
__device__ __forceinline__ u64 pack2(float lo, float hi) {
    u64 r; asm("mov.b64 %0, {%1, %2};" : "=l"(r) : "f"(lo), "f"(hi)); return r;
}
__device__ __forceinline__ void unpack2(u64 v, float &lo, float &hi) {
    asm("mov.b64 {%0, %1}, %2;" : "=f"(lo), "=f"(hi) : "l"(v));
}

// forward products
__device__ float g_Uh [RR*NX*NX];  // [r][j][k] = Uhat[k][j] (valid k<=j; junk below)
__device__ float g_off[RR*NX*NX];  // [r][j][k] = off[j][k]  (row-major off)
__device__ float g_rs [RR*NX];     // rstd diag
__device__ float g_u  [RR*NX];
// prep product
__device__ float g_LI [RR*NX*NX];  // [r][j][i] = Linv[i][j]  (column j per row)

#define AH(k) pa[(k)>>1].f[(k)&1]
#define BH(k) pb[(k)>>1].f[(k)&1]

// ---------------------------------------------------------------------------
// Forward: one WARP per chain (warm-up 3, chunk 8 -> 1024 chains). The 32x65
// augmented system [M | -ap | w] lives column-per-lane in registers; Gaussian
// elimination via warp shuffles — zero block barriers. The M-column
// accumulator is kept as packed f32x2 pairs so the rank-32 pred-downdate
// runs on the f32x2 pipe (16 FFMA2 per k instead of 32 FFMA).
// ---------------------------------------------------------------------------
__global__ __launch_bounds__(128) void fwd_kernel(
    const float* __restrict__ hess, const float* __restrict__ grads,
    const float* __restrict__ Amat, const float* __restrict__ Ptp,
    const float* __restrict__ Pinit)
{
    // packed-by-row-pair column matrices: Xp[t*33+lane] = (X[2t][lane], X[2t+1][lane])
    __shared__ __align__(16) float2 C1p[16*33];   // Ptp + apat
    __shared__ __align__(16) float2 C0p[16*33];   // Ptp (last step)
    __shared__ __align__(16) float2 Cip[16*33];   // Pinit + apat (r==0)
    __shared__ __align__(16) float2 napp[16*33];  // -ap
    __shared__ __align__(16) float offp[FWPB][NX*36+4];  // per-warp offT, stride 36

    const int tid = threadIdx.x, lane = tid & 31, w = tid >> 5;

    // ---- block init: ap = A@Ptp, apat = ap@A^T, build packed C's/nap ----
    {
        float* A_s = offp[0];          // temp (stride 33)
        float* P_s = offp[2];          // temp
        float* napt = (float*)C0p;     // temp scalar -ap (stride 33) in C0p space
        for (int idx = tid; idx < NX*NX; idx += 128) {
            int i = idx >> 5, j = idx & 31;
            A_s[i*33+j] = Amat[idx];
            P_s[i*33+j] = Ptp[idx];
        }
        __syncthreads();
        for (int idx = tid; idx < NX*NX; idx += 128) {  // napt = -(A@P)
            int i = idx >> 5, j = idx & 31;
            float s = 0.f;
            #pragma unroll
            for (int k = 0; k < NX; k++) s += A_s[i*33+k]*P_s[k*33+j];
            napt[i*33+j] = -s;
        }
        __syncthreads();
        for (int idx = tid; idx < NX*NX; idx += 128) {  // apat; packed stores
            int i = idx >> 5, j = idx & 31;
            float s = 0.f;
            #pragma unroll
            for (int k = 0; k < NX; k++) s -= napt[i*33+k]*A_s[j*33+k];
            const float P = P_s[i*33+j];
            const int pi = (i>>1)*33 + j, h = i & 1;
            ((float*)&C1p[pi])[h] = P + s;
            ((float*)&Cip[pi])[h] = Pinit[idx] + s;
            ((float*)&napp[pi])[h] = napt[i*33+j];
        }
        __syncthreads();
        for (int idx = tid; idx < NX*NX; idx += 128) {  // C0p last (frees temp)
            int i = idx >> 5, j = idx & 31;
            const float P = P_s[i*33+j];
            __syncwarp();   // (values already read above in same pass order)
            ((float*)&C0p[(i>>1)*33 + j])[i & 1] = P;
        }
        __syncthreads();
    }

    const int chain = blockIdx.x*FWPB + w;
    const int rmain = chain*FW_S;
    int r0 = rmain - FW_W; if (r0 < 0) r0 = 0;
    const int rend = rmain + FW_S;
    const int nsteps = rend - r0;
    float* op = offp[w];

    F2U pa[16], pb[16], hp2[16];
    float rsd[NX], offr[NX];
    float gv, wv, uacc = 0.f;

    #pragma unroll
    for (int k = 0; k < NX; k++) { offr[k] = 0.f; op[k*36+lane] = 0.f; }
    __syncwarp();

    #pragma unroll
    for (int t = 0; t < 16; t++) {
        hp2[t].f[0] = hess[(size_t)r0*1024 + (2*t)*32 + lane];
        hp2[t].f[1] = hess[(size_t)r0*1024 + (2*t+1)*32 + lane];
    }
    gv = grads[r0*NX + lane];

    for (int step = 0; step < nsteps; step++) {
        const int r = r0 + step;
        const float2* Cp = (r == 0) ? Cip : ((r == RR-1) ? C0p : C1p);

        // ---- build: pa = C + hess (packed), then rank-32 downdate ----
        #pragma unroll
        for (int t = 0; t < 16; t++) {
            u64 c = *(const u64*)&Cp[t*33 + lane];
            pa[t].u = add2(c, hp2[t].u);
            pb[t].u = *(const u64*)&napp[t*33 + lane];
        }
        #pragma unroll
        for (int k = 0; k < NX; k++) {
            const float nok = -offr[k];
            const u64 okk = pack2(nok, nok);
            const float4* opr = (const float4*)&op[k*36];
            #pragma unroll
            for (int q = 0; q < 8; q++) {
                F4U2 v; v.f4 = opr[q];
                ffma2(pa[2*q].u,   v.u2[0], okk);
                ffma2(pa[2*q+1].u, v.u2[1], okk);
            }
        }
        wv = gv - uacc;   // w[lane] = grad[lane] - u . off[lane][:]

        if (step + 1 < nsteps) {   // prefetch next hess/grad under elimination
            #pragma unroll
            for (int t = 0; t < 16; t++) {
                hp2[t].f[0] = hess[(size_t)(r+1)*1024 + (2*t)*32 + lane];
                hp2[t].f[1] = hess[(size_t)(r+1)*1024 + (2*t+1)*32 + lane];
            }
            gv = grads[(r+1)*NX + lane];
        }

        // ---- shuffle elimination (no barriers; scalar ops on pair halves) ----
        float dmine = 1.f;
        #pragma unroll
        for (int k = 0; k < NX; k++) {
            const float dk = __shfl_sync(FULLM, AH(k), k);
            rsd[k] = dk;
            dmine = (lane == k) ? dk : dmine;
            const float invd = __frcp_rn(dk);
            const float ak_s = AH(k)*invd;
            const float bk_s = BH(k)*invd;
            #pragma unroll
            for (int i = k+1; i < NX; i++) {
                const float t = __shfl_sync(FULLM, AH(i), k);
                AH(i) -= t*ak_s;
                BH(i) -= t*bk_s;
            }
        }
        #pragma unroll
        for (int k = 0; k < NX; k++) rsd[k] = __frsqrt_rn(rsd[k]);
        const float rsmine = __frsqrt_rn(dmine);

        // ---- eliminate w: t_ik = Uhat[k][i]*invd_k = a[k]*rs_k^2 (local) ----
        #pragma unroll
        for (int k = 0; k < NX; k++) {
            const float wk = __shfl_sync(FULLM, wv, k);
            const float t = (lane > k) ? AH(k)*rsd[k]*rsd[k] : 0.f;
            wv -= t*wk;
        }

        // ---- extraction: off row, u-dot for next w, smem offT ----
        uacc = 0.f;
        #pragma unroll
        for (int k = 0; k < NX; k++) {
            offr[k] = BH(k)*rsd[k];
            const float uk = __shfl_sync(FULLM, wv, k) * rsd[k];
            uacc += uk*offr[k];
            op[k*36+lane] = offr[k];
        }
        __syncwarp();

        if (r >= rmain) {
            const size_t rb = (size_t)r*(NX*NX) + lane*NX;
            #pragma unroll
            for (int k4 = 0; k4 < NX; k4 += 4) {
                *(float4*)&g_off[rb+k4] = make_float4(offr[k4],offr[k4+1],offr[k4+2],offr[k4+3]);
                *(float4*)&g_Uh [rb+k4] = make_float4(AH(k4),AH(k4+1),AH(k4+2),AH(k4+3));
            }
            g_rs[r*NX+lane] = rsmine;
            g_u [r*NX+lane] = wv * rsmine;
        }
    }
}

// ---------------------------------------------------------------------------
// prep: ONE WARP PER r — invert L entirely in registers via shuffles.
// Lane j computes Linv column j; stores g_LI[r][j][i] = Linv[i][j].
// ---------------------------------------------------------------------------
__global__ __launch_bounds__(256) void prep_kernel()
{
    const int lane = threadIdx.x & 31, w = threadIdx.x >> 5;
    const int r = blockIdx.x*PR_WPB + w;
    const size_t rb = (size_t)r*1024 + lane*32;

    float uc[32];
    #pragma unroll
    for (int k4 = 0; k4 < 32; k4 += 4) {
        float4 v = *(const float4*)&g_Uh[rb + k4];
        uc[k4]=v.x; uc[k4+1]=v.y; uc[k4+2]=v.z; uc[k4+3]=v.w;
    }
    const float rsv = g_rs[r*32 + lane];
    float rsk[32];
    #pragma unroll
    for (int k = 0; k < 32; k++) rsk[k] = __shfl_sync(FULLM, rsv, k);
    #pragma unroll
    for (int k = 0; k < 32; k++) uc[k] *= rsk[k];   // lane i: uc[k] = L[i][k] (k<i)

    float x[32];
    #pragma unroll
    for (int i = 0; i < 32; i++) x[i] = (i == lane) ? rsv : 0.f;
    #pragma unroll
    for (int i = 1; i < 32; i++) {
        float s = 0.f;
        #pragma unroll
        for (int k = 0; k < i; k++) {
            const float Lik = __shfl_sync(FULLM, uc[k], i);
            s += Lik * x[k];
        }
        if (lane < i) x[i] = -rsk[i]*s;
    }
    #pragma unroll
    for (int i4 = 0; i4 < 32; i4 += 4)
        *(float4*)&g_LI[rb + i4] = make_float4(x[i4],x[i4+1],x[i4+2],x[i4+3]);
}

// ---------------------------------------------------------------------------
// Backward: chunked reverse scan (warm-up 5, chunk 32 -> 256 blocks of 256
// threads, 2 blocks/SM = single wave). Per step: vw' = (g - vw@off) @ Linv,
// two warp-private matmul phases; dots run on the f32x2 pipe (FFMA2).
// ---------------------------------------------------------------------------
__global__ __launch_bounds__(BNT, 2) void bwd_kernel(
    const float* __restrict__ epsx, float* __restrict__ out)
{
    __shared__ __align__(16) float vw  [65*VST];
    __shared__ __align__(16) float tmp [65*VST];
    __shared__ __align__(16) float offT_s[NX*VST];  // [j*36+i] = off[i][j]
    __shared__ __align__(16) float li_s  [NX*VST];  // [j*36+k] = Linv[k][j]
    __shared__ float u_s[NX];

    const int tid = threadIdx.x;
    const int b   = blockIdx.x;
    const int lane = tid & 31, w = tid >> 5;   // 8 warps
    const int rlow     = b*BW_S;
    const int rmainTop = rlow + BW_S - 1;
    int rtop = rmainTop + BW_W; if (rtop > RR-1) rtop = RR-1;
    const int nsteps = rtop - rlow + 1;

    for (int idx = tid; idx < 65*VST; idx += BNT) vw[idx] = 0.f;

    float4 pf0, pf1; float uval = 0.f; float gval[9];
    auto prefetch = [&](int r) {
        const size_t rb = (size_t)r*1024;
        pf0 = ((const float4*)(g_off + rb))[tid];
        pf1 = ((const float4*)(g_LI  + rb))[tid];
        if (tid < NX) uval = g_u[r*NX + tid];
        #pragma unroll
        for (int t = 0; t < 9; t++) {
            const int m = w + 8*t;
            if (m >= 1 && m < 65) gval[t] = epsx[(size_t)r*2048 + (m-1)*32 + lane];
        }
    };
    prefetch(rtop);

    for (int step = 0; step < nsteps; step++) {
        const int r = rtop - step;

        // ---- stage tiles: off transposed (scatter), Linv rows (float4) ----
        {
            const int fi = tid*4, j = fi >> 5, k = fi & 31;
            offT_s[(k+0)*VST + j] = pf0.x;
            offT_s[(k+1)*VST + j] = pf0.y;
            offT_s[(k+2)*VST + j] = pf0.z;
            offT_s[(k+3)*VST + j] = pf0.w;
            *(float4*)&li_s[j*VST + k] = pf1;
            if (tid < NX) u_s[tid] = uval;
        }
        float gcur[9];
        #pragma unroll
        for (int t = 0; t < 9; t++) gcur[t] = gval[t];
        if (step + 1 < nsteps) prefetch(r-1);
        __syncthreads();   // staging visible; orders prior output reads vs vw writes

        // lane-cached columns, packed as f32x2 pairs
        u64 ofr2[16], ltr2[16];
        #pragma unroll
        for (int k4 = 0; k4 < NX; k4 += 4) {
            F4U2 v; v.f4 = *(const float4*)&offT_s[lane*VST + k4];   // off[i][lane]
            ofr2[k4>>1] = v.u2[0]; ofr2[(k4>>1)+1] = v.u2[1];
            F4U2 u; u.f4 = *(const float4*)&li_s[lane*VST + k4];     // Linv[k][lane]
            ltr2[k4>>1] = u.u2[0]; ltr2[(k4>>1)+1] = u.u2[1];
        }

        // phase 1: tmp[m][lane] = g[m][lane] - sum_i vw[m][i]*off[i][lane]
        #pragma unroll
        for (int t = 0; t < 9; t++) {
            const int m = w + 8*t;
            if (m < 65) {
                u64 acc = 0;
                const float4* vp = (const float4*)&vw[m*VST];
                #pragma unroll
                for (int q = 0; q < 8; q++) {
                    F4U2 v; v.f4 = vp[q];
                    ffma2(acc, v.u2[0], ofr2[2*q]);
                    ffma2(acc, v.u2[1], ofr2[2*q+1]);
                }
                float lo, hi; unpack2(acc, lo, hi);
                const float g0 = (m == 0) ? u_s[lane] : gcur[t];
                tmp[m*VST + lane] = g0 - (lo + hi);
            }
        }
        __syncwarp();
        // phase 2: vw[m][lane] = sum_k tmp[m][k]*Linv[k][lane]
        #pragma unroll
        for (int t = 0; t < 9; t++) {
            const int m = w + 8*t;
            if (m < 65) {
                u64 acc = 0;
                const float4* tp = (const float4*)&tmp[m*VST];
                #pragma unroll
                for (int q = 0; q < 8; q++) {
                    F4U2 v; v.f4 = tp[q];
                    ffma2(acc, v.u2[0], ltr2[2*q]);
                    ffma2(acc, v.u2[1], ltr2[2*q+1]);
                }
                float lo, hi; unpack2(acc, lo, hi);
                vw[m*VST + lane] = lo + hi;
            }
        }
        __syncthreads();   // vw complete before cross-warp output read

        if (r <= rmainTop) {
            float* orow = out + (size_t)r * 2048;
            #pragma unroll
            for (int t = 0; t < 8; t++) {
                const int idx = tid + BNT*t;
                const int m = idx >> 5, i = idx & 31;
                orow[idx] = vw[i] + vw[(m+1)*VST + i];
            }
        }
    }
}

extern "C" void kernel_launch(void* const* d_in, const int* in_sizes, int n_in,
                              void* d_out, int out_size) {
    const float* hess  = (const float*)d_in[0];   // (8192,32,32)
    const float* grads = (const float*)d_in[1];   // (8192,1,32)
    const float* Amat  = (const float*)d_in[2];   // (32,32)
    const float* Ptp   = (const float*)d_in[3];   // (32,32)
    const float* Pinit = (const float*)d_in[4];   // (32,32)
    const float* epsx  = (const float*)d_in[5];   // (8192,64,32)
    float* out = (float*)d_out;                   // (8192,64,32)
    (void)in_sizes; (void)n_in; (void)out_size;

    fwd_kernel<<<FW_BLOCKS, 128>>>(hess, grads, Amat, Ptp, Pinit);
    prep_kernel<<<RR/PR_WPB, 256>>>();
    bwd_kernel<<<BW_BLOCKS, BNT>>>(epsx, out);
}

// round 17
// speedup vs baseline: 1.5485x; 1.5485x over previous
#include <cuda_runtime.h>
#include <cstdint>

#define RR 8192
#define NX 32
#define FW_S 8
#define FW_W 3
#define NCHAIN (RR/FW_S)         // 1024 chains, one warp each
#define FWPB 4                   // warps per block
#define FW_BLOCKS (NCHAIN/FWPB)  // 256
#define BW_S 32
#define BW_W 5
#define BW_BLOCKS (RR/BW_S)      // 256
#define BNT 256
#define PR_WPB 8
#define VST 36                   // vw/tmp/offT/li row stride (16B aligned)
#define FULLM 0xffffffffu

// forward products
__device__ float g_Uh [RR*NX*NX];  // [r][j][k] = Uhat[k][j] (valid k<=j; junk below)
__device__ float g_off[RR*NX*NX];  // [r][j][k] = off[j][k]  (row-major off)
__device__ float g_rs [RR*NX];     // rstd diag
__device__ float g_u  [RR*NX];
// prep product
__device__ float g_LI [RR*NX*NX];  // [r][j][i] = Linv[i][j]  (column j per row)

// ---------------------------------------------------------------------------
// Forward: one WARP per chain (warm-up 3, chunk 8 -> 1024 chains). The 32x65
// augmented system [M | -ap | w] lives column-per-lane in registers; Gaussian
// elimination via warp shuffles — zero block barriers. (Scalar registers:
// the R16 f32x2-packed variant spilled to local memory and regressed 2x.)
// ---------------------------------------------------------------------------
__global__ __launch_bounds__(128) void fwd_kernel(
    const float* __restrict__ hess, const float* __restrict__ grads,
    const float* __restrict__ Amat, const float* __restrict__ Ptp,
    const float* __restrict__ Pinit)
{
    __shared__ __align__(16) float C1[NX*33];     // Ptp + apat   (columns: [i*33+j])
    __shared__ __align__(16) float C0[NX*33];     // Ptp          (last step, mfac=0)
    __shared__ __align__(16) float Ci[NX*33];     // Pinit + apat (r==0)
    __shared__ __align__(16) float nap[NX*33];    // -ap
    __shared__ __align__(16) float offp[FWPB][NX*36+4];  // per-warp offT, stride 36

    const int tid = threadIdx.x, lane = tid & 31, w = tid >> 5;

    // ---- block init: ap = A@Ptp, apat = ap@A^T, build C0/C1/Ci/nap ----
    {
        float* A_s = offp[0];          // temp (stride 33)
        float* P_s = offp[2];          // temp
        for (int idx = tid; idx < NX*NX; idx += 128) {
            int i = idx >> 5, j = idx & 31;
            A_s[i*33+j] = Amat[idx];
            P_s[i*33+j] = Ptp[idx];
        }
        __syncthreads();
        for (int idx = tid; idx < NX*NX; idx += 128) {  // nap = -(A@P)
            int i = idx >> 5, j = idx & 31;
            float s = 0.f;
            #pragma unroll
            for (int k = 0; k < NX; k++) s += A_s[i*33+k]*P_s[k*33+j];
            nap[i*33+j] = -s;
        }
        __syncthreads();
        for (int idx = tid; idx < NX*NX; idx += 128) {  // apat = ap@A^T; C's
            int i = idx >> 5, j = idx & 31;
            float s = 0.f;
            #pragma unroll
            for (int k = 0; k < NX; k++) s -= nap[i*33+k]*A_s[j*33+k];
            const float P = P_s[i*33+j];
            C1[i*33+j] = P + s;
            C0[i*33+j] = P;
            Ci[i*33+j] = Pinit[idx] + s;
        }
        __syncthreads();
    }

    const int chain = blockIdx.x*FWPB + w;
    const int rmain = chain*FW_S;
    int r0 = rmain - FW_W; if (r0 < 0) r0 = 0;
    const int nsteps = rmain + FW_S - r0;
    float* op = offp[w];

    float a[NX], b[NX], rsd[NX], offr[NX], hp[NX];
    float gv, wv, uacc = 0.f;

    #pragma unroll
    for (int k = 0; k < NX; k++) { offr[k] = 0.f; op[k*36+lane] = 0.f; }
    __syncwarp();

    #pragma unroll
    for (int i = 0; i < NX; i++) hp[i] = hess[(size_t)r0*1024 + i*32 + lane];
    gv = grads[r0*NX + lane];

    for (int step = 0; step < nsteps; step++) {
        const int r = r0 + step;
        const float* Cp = (r == 0) ? Ci : ((r == RR-1) ? C0 : C1);

        // ---- build: a = C + hess - off^T off   (col of M), b = -ap col ----
        #pragma unroll
        for (int i = 0; i < NX; i++) a[i] = Cp[i*33+lane] + hp[i];
        #pragma unroll
        for (int k = 0; k < NX; k++) {
            const float ok = offr[k];
            #pragma unroll
            for (int i4 = 0; i4 < NX; i4 += 4) {
                const float4 v = *(const float4*)&op[k*36 + i4];
                a[i4]   -= v.x*ok; a[i4+1] -= v.y*ok;
                a[i4+2] -= v.z*ok; a[i4+3] -= v.w*ok;
            }
        }
        #pragma unroll
        for (int i = 0; i < NX; i++) b[i] = nap[i*33+lane];
        wv = gv - uacc;   // w[lane] = grad[lane] - u . off[lane][:]

        if (step + 1 < nsteps) {   // prefetch next hess/grad under elimination
            #pragma unroll
            for (int i = 0; i < NX; i++) hp[i] = hess[(size_t)(r+1)*1024 + i*32 + lane];
            gv = grads[(r+1)*NX + lane];
        }

        // ---- shuffle elimination (no barriers, no per-update multiply) ----
        float dmine = 1.f;
        #pragma unroll
        for (int k = 0; k < NX; k++) {
            const float dk = __shfl_sync(FULLM, a[k], k);
            rsd[k] = dk;
            dmine = (lane == k) ? dk : dmine;
            const float invd = __frcp_rn(dk);
            const float ak_s = a[k]*invd;   // lane-local scaled pivot row entries
            const float bk_s = b[k]*invd;
            #pragma unroll
            for (int i = k+1; i < NX; i++) {
                const float t = __shfl_sync(FULLM, a[i], k);
                a[i] -= t*ak_s;
                b[i] -= t*bk_s;
            }
        }
        #pragma unroll
        for (int k = 0; k < NX; k++) rsd[k] = __frsqrt_rn(rsd[k]);
        const float rsmine = __frsqrt_rn(dmine);

        // ---- eliminate w: t_ik = Uhat[k][i]*invd_k = a[k]*rs_k^2 (local) ----
        #pragma unroll
        for (int k = 0; k < NX; k++) {
            const float wk = __shfl_sync(FULLM, wv, k);
            const float t = (lane > k) ? a[k]*rsd[k]*rsd[k] : 0.f;
            wv -= t*wk;
        }

        // ---- extraction: off row, u-dot for next w, smem offT ----
        uacc = 0.f;
        #pragma unroll
        for (int k = 0; k < NX; k++) {
            offr[k] = b[k]*rsd[k];
            const float uk = __shfl_sync(FULLM, wv, k) * rsd[k];
            uacc += uk*offr[k];
            op[k*36+lane] = offr[k];
        }
        __syncwarp();

        if (r >= rmain) {
            const size_t rb = (size_t)r*(NX*NX) + lane*NX;
            #pragma unroll
            for (int k4 = 0; k4 < NX; k4 += 4) {
                *(float4*)&g_off[rb+k4] = make_float4(offr[k4],offr[k4+1],offr[k4+2],offr[k4+3]);
                *(float4*)&g_Uh [rb+k4] = make_float4(a[k4],a[k4+1],a[k4+2],a[k4+3]);
            }
            g_rs[r*NX+lane] = rsmine;
            g_u [r*NX+lane] = wv * rsmine;
        }
    }
}

// ---------------------------------------------------------------------------
// prep: ONE WARP PER r — invert L entirely in registers via shuffles.
// Lane j computes Linv column j; stores g_LI[r][j][i] = Linv[i][j].
// ---------------------------------------------------------------------------
__global__ __launch_bounds__(256) void prep_kernel()
{
    const int lane = threadIdx.x & 31, w = threadIdx.x >> 5;
    const int r = blockIdx.x*PR_WPB + w;
    const size_t rb = (size_t)r*1024 + lane*32;

    float uc[32];
    #pragma unroll
    for (int k4 = 0; k4 < 32; k4 += 4) {
        float4 v = *(const float4*)&g_Uh[rb + k4];
        uc[k4]=v.x; uc[k4+1]=v.y; uc[k4+2]=v.z; uc[k4+3]=v.w;
    }
    const float rsv = g_rs[r*32 + lane];
    float rsk[32];
    #pragma unroll
    for (int k = 0; k < 32; k++) rsk[k] = __shfl_sync(FULLM, rsv, k);
    #pragma unroll
    for (int k = 0; k < 32; k++) uc[k] *= rsk[k];   // lane i: uc[k] = L[i][k] (k<i)

    float x[32];
    #pragma unroll
    for (int i = 0; i < 32; i++) x[i] = (i == lane) ? rsv : 0.f;
    #pragma unroll
    for (int i = 1; i < 32; i++) {
        float s = 0.f;
        #pragma unroll
        for (int k = 0; k < i; k++) {
            const float Lik = __shfl_sync(FULLM, uc[k], i);
            s += Lik * x[k];
        }
        if (lane < i) x[i] = -rsk[i]*s;
    }
    #pragma unroll
    for (int i4 = 0; i4 < 32; i4 += 4)
        *(float4*)&g_LI[rb + i4] = make_float4(x[i4],x[i4+1],x[i4+2],x[i4+3]);
}

// ---------------------------------------------------------------------------
// Backward: chunked reverse scan (warm-up 5, chunk 32 -> 256 blocks of 256
// threads, 2 blocks/SM = single wave). Per step: vw' = (g - vw@off) @ Linv,
// two warp-private matmul phases, float4 broadcast loads throughout.
// ---------------------------------------------------------------------------
__global__ __launch_bounds__(BNT, 2) void bwd_kernel(
    const float* __restrict__ epsx, float* __restrict__ out)
{
    __shared__ __align__(16) float vw  [65*VST];
    __shared__ __align__(16) float tmp [65*VST];
    __shared__ __align__(16) float offT_s[NX*VST];  // [j*36+i] = off[i][j]
    __shared__ __align__(16) float li_s  [NX*VST];  // [j*36+k] = Linv[k][j]
    __shared__ float u_s[NX];

    const int tid = threadIdx.x;
    const int b   = blockIdx.x;
    const int lane = tid & 31, w = tid >> 5;   // 8 warps
    const int rlow     = b*BW_S;
    const int rmainTop = rlow + BW_S - 1;
    int rtop = rmainTop + BW_W; if (rtop > RR-1) rtop = RR-1;
    const int nsteps = rtop - rlow + 1;

    for (int idx = tid; idx < 65*VST; idx += BNT) vw[idx] = 0.f;

    float4 pf0, pf1; float uval = 0.f; float gval[9];
    auto prefetch = [&](int r) {
        const size_t rb = (size_t)r*1024;
        pf0 = ((const float4*)(g_off + rb))[tid];
        pf1 = ((const float4*)(g_LI  + rb))[tid];
        if (tid < NX) uval = g_u[r*NX + tid];
        #pragma unroll
        for (int t = 0; t < 9; t++) {
            const int m = w + 8*t;
            if (m >= 1 && m < 65) gval[t] = epsx[(size_t)r*2048 + (m-1)*32 + lane];
        }
    };
    prefetch(rtop);

    for (int step = 0; step < nsteps; step++) {
        const int r = rtop - step;

        // ---- stage tiles: off transposed (scatter), Linv rows (float4) ----
        {
            const int fi = tid*4, j = fi >> 5, k = fi & 31;
            offT_s[(k+0)*VST + j] = pf0.x;
            offT_s[(k+1)*VST + j] = pf0.y;
            offT_s[(k+2)*VST + j] = pf0.z;
            offT_s[(k+3)*VST + j] = pf0.w;
            *(float4*)&li_s[j*VST + k] = pf1;
            if (tid < NX) u_s[tid] = uval;
        }
        float gcur[9];
        #pragma unroll
        for (int t = 0; t < 9; t++) gcur[t] = gval[t];
        if (step + 1 < nsteps) prefetch(r-1);
        __syncthreads();   // staging visible; orders prior output reads vs vw writes

        // lane-cached columns (both float4)
        float ofr[NX], ltr[NX];
        #pragma unroll
        for (int k4 = 0; k4 < NX; k4 += 4) {
            const float4 v = *(const float4*)&offT_s[lane*VST + k4];  // off[i][lane]
            ofr[k4]=v.x; ofr[k4+1]=v.y; ofr[k4+2]=v.z; ofr[k4+3]=v.w;
            const float4 u = *(const float4*)&li_s[lane*VST + k4];    // Linv[k][lane]
            ltr[k4]=u.x; ltr[k4+1]=u.y; ltr[k4+2]=u.z; ltr[k4+3]=u.w;
        }

        // phase 1: tmp[m][lane] = g[m][lane] - sum_i vw[m][i]*off[i][lane]
        #pragma unroll
        for (int t = 0; t < 9; t++) {
            const int m = w + 8*t;
            if (m < 65) {
                float s = (m == 0) ? u_s[lane] : gcur[t];
                const float4* vp = (const float4*)&vw[m*VST];
                #pragma unroll
                for (int q = 0; q < 8; q++) {
                    const float4 v4 = vp[q];
                    s -= v4.x*ofr[4*q] + v4.y*ofr[4*q+1] + v4.z*ofr[4*q+2] + v4.w*ofr[4*q+3];
                }
                tmp[m*VST + lane] = s;
            }
        }
        __syncwarp();
        // phase 2: vw[m][lane] = sum_k tmp[m][k]*Linv[k][lane]
        #pragma unroll
        for (int t = 0; t < 9; t++) {
            const int m = w + 8*t;
            if (m < 65) {
                float s = 0.f;
                const float4* tp = (const float4*)&tmp[m*VST];
                #pragma unroll
                for (int q = 0; q < 8; q++) {
                    const float4 t4 = tp[q];
                    s += t4.x*ltr[4*q] + t4.y*ltr[4*q+1] + t4.z*ltr[4*q+2] + t4.w*ltr[4*q+3];
                }
                vw[m*VST + lane] = s;
            }
        }
        __syncthreads();   // vw complete before cross-warp output read

        if (r <= rmainTop) {
            float* orow = out + (size_t)r * 2048;
            #pragma unroll
            for (int t = 0; t < 8; t++) {
                const int idx = tid + BNT*t;
                const int m = idx >> 5, i = idx & 31;
                orow[idx] = vw[i] + vw[(m+1)*VST + i];
            }
        }
    }
}

extern "C" void kernel_launch(void* const* d_in, const int* in_sizes, int n_in,
                              void* d_out, int out_size) {
    const float* hess  = (const float*)d_in[0];   // (8192,32,32)
    const float* grads = (const float*)d_in[1];   // (8192,1,32)
    const float* Amat  = (const float*)d_in[2];   // (32,32)
    const float* Ptp   = (const float*)d_in[3];   // (32,32)
    const float* Pinit = (const float*)d_in[4];   // (32,32)
    const float* epsx  = (const float*)d_in[5];   // (8192,64,32)
    float* out = (float*)d_out;                   // (8192,64,32)
    (void)in_sizes; (void)n_in; (void)out_size;

    fwd_kernel<<<FW_BLOCKS, 128>>>(hess, grads, Amat, Ptp, Pinit);
    prep_kernel<<<RR/PR_WPB, 256>>>();
    bwd_kernel<<<BW_BLOCKS, BNT>>>(epsx, out);
}